// round 7
// baseline (speedup 1.0000x reference)
#include <cuda_runtime.h>
#include <cuda_bf16.h>
#include <math.h>

// Problem shapes (fixed by the dataset)
#define BDIM 8
#define NDIM 8192
#define CDIM 256
#define HDIM 256
#define ODIM 256
#define KDIM 64
#define KCHUNK 4
#define NCHUNKS (KDIM / KCHUNK)   // 16
#define OTILE 32                  // o-outputs per k2 block
#define NOBLK (ODIM / OTILE)      // 8
#define CONC (CDIM + HDIM)        // 512
#define LEAKY_ALPHA 0.3f
#define EPS 1e-6f

// Global scratch (__device__ arrays; no allocation)
__device__ float g_partial[BDIM * NCHUNKS * HDIM];  // per-(b,chunk) weighted hidden sums
__device__ float g_wsum[BDIM * NCHUNKS];            // per-(b,chunk) sum of neighbor weights
__device__ float g_hidden[BDIM * ODIM];             // per-b pre-norm hidden
__device__ float g_ssq[BDIM * NOBLK];               // per-(b, o-block) sum-of-squares partial

__device__ __forceinline__ float leaky(float x) {
    return x >= 0.0f ? x : LEAKY_ALPHA * x;
}

// ---------------------------------------------------------------------------
// Kernel 1: grid (16 chunks, 8 b), 256 threads.
//   th = tid&63 : h-group of 4 (float4 on Qw rows)
//   tc = tid>>6 : c-quarter (64 c each)
// Each thread keeps 4 accumulators (one per neighbor) so each Qw load feeds
// 16 FMAs — Qw is read exactly once per block. Partials over tc are combined
// BEFORE bias+leaky (nonlinearity needs the full dot).
// ---------------------------------------------------------------------------
__global__ void __launch_bounds__(256, 1)
k1_neighbor_hidden(const float* __restrict__ emb,
                   const float* __restrict__ weights,
                   const float* __restrict__ Qw,
                   const float* __restrict__ Qb,
                   const int*   __restrict__ nb,
                   const int*   __restrict__ nid_p)
{
    const int chunk = blockIdx.x;   // 0..15
    const int b     = blockIdx.y;   // 0..7
    const int tid   = threadIdx.x;
    const int th    = tid & 63;     // h-group
    const int tc    = tid >> 6;     // c-quarter 0..3

    __shared__ float  embs[KCHUNK][CDIM];       // 4 KB
    __shared__ float  ws[KCHUNK];
    __shared__ int    nbs[KCHUNK];
    __shared__ float4 part[4][KCHUNK][64];      // 16 KB  [tc][k][th]

    const int nid = *nid_p;

    if (tid < KCHUNK) {
        int n = nb[chunk * KCHUNK + tid];
        nbs[tid] = n;
        ws[tid] = weights[(size_t)n * NDIM + nid];
    }
    __syncthreads();

    // Cooperative load of 4 embedding rows (256 float4)
    {
        int r = tid >> 6, col = tid & 63;
        ((float4*)embs[r])[col] =
            ((const float4*)(emb + ((size_t)b * NDIM + nbs[r]) * CDIM))[col];
    }
    __syncthreads();

    const float4* Qw4 = (const float4*)Qw + (size_t)tc * 64 * 64;
    const int c0 = tc * 64;

    float4 a0 = make_float4(0.f,0.f,0.f,0.f);
    float4 a1 = make_float4(0.f,0.f,0.f,0.f);
    float4 a2 = make_float4(0.f,0.f,0.f,0.f);
    float4 a3 = make_float4(0.f,0.f,0.f,0.f);

    #pragma unroll 8
    for (int i = 0; i < 64; i++) {
        const int c = c0 + i;
        float4 q = __ldg(&Qw4[i * 64 + th]);
        float e0 = embs[0][c], e1 = embs[1][c], e2 = embs[2][c], e3 = embs[3][c];
        a0.x = fmaf(e0,q.x,a0.x); a0.y = fmaf(e0,q.y,a0.y); a0.z = fmaf(e0,q.z,a0.z); a0.w = fmaf(e0,q.w,a0.w);
        a1.x = fmaf(e1,q.x,a1.x); a1.y = fmaf(e1,q.y,a1.y); a1.z = fmaf(e1,q.z,a1.z); a1.w = fmaf(e1,q.w,a1.w);
        a2.x = fmaf(e2,q.x,a2.x); a2.y = fmaf(e2,q.y,a2.y); a2.z = fmaf(e2,q.z,a2.z); a2.w = fmaf(e2,q.w,a2.w);
        a3.x = fmaf(e3,q.x,a3.x); a3.y = fmaf(e3,q.y,a3.y); a3.z = fmaf(e3,q.z,a3.z); a3.w = fmaf(e3,q.w,a3.w);
    }
    part[tc][0][th] = a0;
    part[tc][1][th] = a1;
    part[tc][2][th] = a2;
    part[tc][3][th] = a3;
    __syncthreads();

    // Combine c-quarters, apply bias+leaky+weight. (k,h) disjoint per thread.
    {
        int k = tid >> 6, h = tid & 63;
        float4 s  = part[0][k][h];
        float4 p1 = part[1][k][h], p2 = part[2][k][h], p3 = part[3][k][h];
        s.x += p1.x + p2.x + p3.x;
        s.y += p1.y + p2.y + p3.y;
        s.z += p1.z + p2.z + p3.z;
        s.w += p1.w + p2.w + p3.w;
        float4 qb = ((const float4*)Qb)[h];
        float  w  = ws[k];
        float4 r;
        r.x = leaky(s.x + qb.x) * w;
        r.y = leaky(s.y + qb.y) * w;
        r.z = leaky(s.z + qb.z) * w;
        r.w = leaky(s.w + qb.w) * w;
        part[0][k][h] = r;
    }
    __syncthreads();

    // Sum 4 neighbors -> g_partial; also record this chunk's weight sum.
    if (tid < 64) {
        float4 s0 = part[0][0][tid], s1 = part[0][1][tid];
        float4 s2 = part[0][2][tid], s3 = part[0][3][tid];
        float4 s;
        s.x = s0.x + s1.x + s2.x + s3.x;
        s.y = s0.y + s1.y + s2.y + s3.y;
        s.z = s0.z + s1.z + s2.z + s3.z;
        s.w = s0.w + s1.w + s2.w + s3.w;
        ((float4*)(g_partial + ((size_t)b * NCHUNKS + chunk) * HDIM))[tid] = s;
    }
    if (tid == 0) {
        g_wsum[b * NCHUNKS + chunk] = ws[0] + ws[1] + ws[2] + ws[3];
    }
}

// ---------------------------------------------------------------------------
// Kernel 2: grid 8 (o-tiles of 32), 1024 threads.
// Phase A: build concat for ALL 8 batches in smem:
//   tid<512        : node embedding float4 (b = tid>>6, col = tid&63)
//   all threads    : raw hidden sums for 2 (b,h) pairs (p = tid, tid+1024)
//   tid in [512,520): denom[b] from g_wsum
// Phase B: GEMV — block handles o-tile of 32 for all 8 batches:
//   og = tid&7, bb = (tid>>3)&7, cq = tid>>6 (16 c-chunks of 32).
//   Warp lanes span og x b at fixed c -> each warp Ww load = ONE 128B line.
// ---------------------------------------------------------------------------
__global__ void __launch_bounds__(1024, 1)
k2_gemv(const float* __restrict__ emb,
        const float* __restrict__ Ww,
        const float* __restrict__ Wb,
        const int*   __restrict__ nid_p)
{
    const int obase4 = blockIdx.x * (OTILE / 4);  // float4 o-base (8 per block)
    const int tid = threadIdx.x;

    __shared__ float  cs[BDIM][CONC];    // 16 KB
    __shared__ float  dn[BDIM];
    __shared__ float4 red[16][64];       // 16 KB  [cq][bb*8+og]
    __shared__ float  sq[64];

    const int nid = *nid_p;

    // --- Phase A ---
    if (tid < 512) {
        int bn = tid >> 6, col = tid & 63;
        ((float4*)cs[bn])[col] =
            ((const float4*)(emb + ((size_t)bn * NDIM + nid) * CDIM))[col];
    }

    // raw hidden sums (2 pairs per thread; coalesced over h)
    float s0 = 0.f, s1 = 0.f;
    {
        const int b0 = tid >> 8,       h0 = tid & 255;
        const int b1 = (tid >> 8) + 4, h1 = tid & 255;
        const float* gp0 = g_partial + ((size_t)b0 * NCHUNKS) * HDIM + h0;
        const float* gp1 = g_partial + ((size_t)b1 * NCHUNKS) * HDIM + h1;
        #pragma unroll
        for (int ch = 0; ch < NCHUNKS; ch++) {
            s0 += gp0[ch * HDIM];
            s1 += gp1[ch * HDIM];
        }
    }

    if (tid >= 512 && tid < 512 + BDIM) {
        const int bn = tid - 512;
        float d = 0.0f;
        #pragma unroll
        for (int i = 0; i < NCHUNKS; i++) d += g_wsum[bn * NCHUNKS + i];
        dn[bn] = d + EPS;
    }
    __syncthreads();

    {
        const int b0 = tid >> 8,       h0 = tid & 255;
        const int b1 = (tid >> 8) + 4;
        cs[b0][CDIM + h0] = s0 / dn[b0];
        cs[b1][CDIM + h0] = s1 / dn[b1];
    }
    __syncthreads();

    // --- Phase B: GEMV ---
    const int og = tid & 7;
    const int bb = (tid >> 3) & 7;
    const int cq = tid >> 6;       // 0..15

    const float4* Ww4 = (const float4*)Ww;
    const float*  e   = cs[bb];
    const int c0 = cq * 32;

    float4 acc = make_float4(0.f,0.f,0.f,0.f);
    #pragma unroll 8
    for (int c = c0; c < c0 + 32; c++) {
        float  ev = e[c];
        float4 q  = __ldg(&Ww4[c * 64 + obase4 + og]);
        acc.x = fmaf(ev, q.x, acc.x);
        acc.y = fmaf(ev, q.y, acc.y);
        acc.z = fmaf(ev, q.z, acc.z);
        acc.w = fmaf(ev, q.w, acc.w);
    }
    red[cq][bb * 8 + og] = acc;
    __syncthreads();

    if (tid < 64) {
        const int b2 = tid >> 3, og2 = tid & 7;
        float4 s = red[0][tid];
        #pragma unroll
        for (int i = 1; i < 16; i++) {
            float4 r = red[i][tid];
            s.x += r.x; s.y += r.y; s.z += r.z; s.w += r.w;
        }
        float4 wb = ((const float4*)Wb)[obase4 + og2];
        float4 v;
        v.x = leaky(s.x + wb.x);
        v.y = leaky(s.y + wb.y);
        v.z = leaky(s.z + wb.z);
        v.w = leaky(s.w + wb.w);
        ((float4*)(g_hidden + (size_t)b2 * ODIM))[obase4 + og2] = v;
        sq[tid] = v.x*v.x + v.y*v.y + v.z*v.z + v.w*v.w;
    }
    __syncthreads();

    if (tid < 8) {  // one per batch: sum this block's 8 og partials
        float t = 0.0f;
        #pragma unroll
        for (int i = 0; i < 8; i++) t += sq[tid * 8 + i];
        g_ssq[tid * NOBLK + blockIdx.x] = t;
    }
}

// ---------------------------------------------------------------------------
// Kernel 3: grid 8, 64 threads. Normalize and store.
// NOTE: the shuffle reduction is executed by ALL 32 lanes of warp 0 (lanes
// >= NOBLK contribute 0) — a partial-warp __shfl_xor_sync with a full mask
// deadlocks on sm_103a.
// ---------------------------------------------------------------------------
__global__ void __launch_bounds__(64, 1)
k3_norm(float* __restrict__ out)
{
    const int b   = blockIdx.x;
    const int tid = threadIdx.x;
    __shared__ float inv_s;

    float4 v = ((const float4*)(g_hidden + (size_t)b * ODIM))[tid];

    if (tid < 32) {   // entire warp 0 participates in the shuffles
        float t = (tid < NOBLK) ? g_ssq[b * NOBLK + tid] : 0.0f;
        #pragma unroll
        for (int off = 4; off > 0; off >>= 1)
            t += __shfl_xor_sync(0xFFFFFFFFu, t, off);
        if (tid == 0) inv_s = 1.0f / (sqrtf(t) + EPS);
    }
    __syncthreads();

    const float inv = inv_s;
    v.x *= inv; v.y *= inv; v.z *= inv; v.w *= inv;
    ((float4*)(out + (size_t)b * ODIM))[tid] = v;
}

extern "C" void kernel_launch(void* const* d_in, const int* in_sizes, int n_in,
                              void* d_out, int out_size)
{
    const float* emb     = (const float*)d_in[0];
    const float* weights = (const float*)d_in[1];
    const float* Qw      = (const float*)d_in[2];
    const float* Qb      = (const float*)d_in[3];
    const float* Ww      = (const float*)d_in[4];
    const float* Wb      = (const float*)d_in[5];
    const int*   nb      = (const int*)d_in[6];
    const int*   nid     = (const int*)d_in[7];
    float*       out     = (float*)d_out;

    dim3 g1(NCHUNKS, BDIM);   // 16 x 8 = 128 blocks
    k1_neighbor_hidden<<<g1, 256>>>(emb, weights, Qw, Qb, nb, nid);
    k2_gemv<<<NOBLK, 1024>>>(emb, Ww, Wb, nid);
    k3_norm<<<BDIM, 64>>>(out);
}